// round 1
// baseline (speedup 1.0000x reference)
#include <cuda_runtime.h>
#include <math.h>
#include <stddef.h>

namespace {
constexpr int Bsz = 1024;
constexpr int Ssz = 64;
constexpr int Dsz = 300;
constexpr int Hsz = 512;
constexpr int Gsz = 1536;   // 3H
constexpr int Zsz = 128;
constexpr int MR  = Bsz * Ssz;   // 65536
constexpr int Rr  = 8;           // batch rows per GRU CTA
}

// Scratch (allocation-free rule: __device__ globals)
__device__ float g_GI[(size_t)2 * MR * Gsz];      // [dir][b*S + t_src][3H], ~805 MB
__device__ float g_part[(size_t)2 * Bsz * Hsz];   // masked hidden sums per direction

__device__ __forceinline__ float dot4(float4 w, float4 h, float a) {
    a = fmaf(w.x, h.x, a);
    a = fmaf(w.y, h.y, a);
    a = fmaf(w.z, h.z, a);
    a = fmaf(w.w, h.w, a);
    return a;
}

__device__ __forceinline__ float sigm(float x) {
    return 1.f / (1.f + __expf(-x));
}

// ---------------------------------------------------------------------------
// Kernel 1: GI = X @ Wih.T + bih for BOTH directions in one GEMM.
// M = B*S = 65536, N = 2*1536 = 3072 (n<1536 -> fwd weights, else bwd), K = 300.
// Tiles: BM=128, BN=64, BK=8, 256 threads, 8x4 per-thread tile.
// ---------------------------------------------------------------------------
__global__ __launch_bounds__(256) void k_gi_gemm(
    const float* __restrict__ X,
    const float* __restrict__ Wf, const float* __restrict__ bf,
    const float* __restrict__ Wb, const float* __restrict__ bb)
{
    __shared__ float As[8][128];
    __shared__ float Bs[8][64];
    const int tid = threadIdx.x;
    const int m0 = blockIdx.x * 128;
    const int n0 = blockIdx.y * 64;
    const int dir = (n0 >= Gsz) ? 1 : 0;
    const float* __restrict__ W    = dir ? Wb : Wf;
    const float* __restrict__ bias = dir ? bb : bf;
    const int g0 = n0 - dir * Gsz;

    const int tx = tid & 15;   // 16 col-groups of 4
    const int ty = tid >> 4;   // 16 row-groups of 8

    float acc[8][4];
    #pragma unroll
    for (int i = 0; i < 8; i++)
        #pragma unroll
        for (int j = 0; j < 4; j++) acc[i][j] = 0.f;

    const int arow = tid >> 1;
    const int half = tid & 1;
    const int brow = (tid & 127) >> 1;

    const float* aptr = X + (size_t)(m0 + arow) * Dsz + half * 4;
    const float* bptr = W + (size_t)(g0 + brow) * Dsz + half * 4;

    for (int k0 = 0; k0 < Dsz; k0 += 8) {
        float4 av = make_float4(0.f, 0.f, 0.f, 0.f);
        if (k0 + half * 4 < Dsz) av = *(const float4*)(aptr + k0);
        As[half*4+0][arow] = av.x;
        As[half*4+1][arow] = av.y;
        As[half*4+2][arow] = av.z;
        As[half*4+3][arow] = av.w;
        if (tid < 128) {
            float4 bv = make_float4(0.f, 0.f, 0.f, 0.f);
            if (k0 + half * 4 < Dsz) bv = *(const float4*)(bptr + k0);
            Bs[half*4+0][brow] = bv.x;
            Bs[half*4+1][brow] = bv.y;
            Bs[half*4+2][brow] = bv.z;
            Bs[half*4+3][brow] = bv.w;
        }
        __syncthreads();
        #pragma unroll
        for (int kk = 0; kk < 8; kk++) {
            float4 a0 = *(const float4*)&As[kk][ty*8];
            float4 a1 = *(const float4*)&As[kk][ty*8+4];
            float4 b  = *(const float4*)&Bs[kk][tx*4];
            float a[8] = {a0.x, a0.y, a0.z, a0.w, a1.x, a1.y, a1.z, a1.w};
            #pragma unroll
            for (int i = 0; i < 8; i++) {
                acc[i][0] = fmaf(a[i], b.x, acc[i][0]);
                acc[i][1] = fmaf(a[i], b.y, acc[i][1]);
                acc[i][2] = fmaf(a[i], b.z, acc[i][2]);
                acc[i][3] = fmaf(a[i], b.w, acc[i][3]);
            }
        }
        __syncthreads();
    }

    const float4 bv = *(const float4*)(bias + g0 + tx*4);
    #pragma unroll
    for (int i = 0; i < 8; i++) {
        size_t m = (size_t)(m0 + ty*8 + i);
        float4 o;
        o.x = acc[i][0] + bv.x;
        o.y = acc[i][1] + bv.y;
        o.z = acc[i][2] + bv.z;
        o.w = acc[i][3] + bv.w;
        *(float4*)(g_GI + ((size_t)dir * MR + m) * Gsz + g0 + tx*4) = o;
    }
}

// ---------------------------------------------------------------------------
// Kernel 2: GRU recurrence, one CTA per (direction, 8 batch rows).
// Thread tid owns hidden units j0=tid and j1=tid+256; accumulates the three
// gate dot-products (r,z,n) against smem-resident h for all 8 rows.
// Double-buffered h in smem -> one __syncthreads per step.
// Accumulates masked sum of h over steps (roll/reverse is sum-invariant).
// ---------------------------------------------------------------------------
__global__ __launch_bounds__(256) void k_gru(
    const float* __restrict__ Whh_f, const float* __restrict__ bhh_f,
    const float* __restrict__ Whh_b, const float* __restrict__ bhh_b,
    const int* __restrict__ lens)
{
    __shared__ float hsA[Rr][Hsz];
    __shared__ float hsB[Rr][Hsz];
    __shared__ int slen[Rr];

    const int tid = threadIdx.x;
    const int dir = blockIdx.y;
    const int b0 = blockIdx.x * Rr;
    const float* __restrict__ Whh = dir ? Whh_b : Whh_f;
    const float* __restrict__ bhh = dir ? bhh_b : bhh_f;
    const float* __restrict__ GIb = g_GI + (size_t)dir * MR * Gsz;

    if (tid < Rr) slen[tid] = lens[b0 + tid];
    for (int i = tid; i < Rr * Hsz; i += 256) (&hsA[0][0])[i] = 0.f;

    const int j0 = tid;
    const int j1 = tid + 256;

    const float4* __restrict__ WR0 = (const float4*)(Whh + (size_t)j0 * Hsz);
    const float4* __restrict__ WZ0 = (const float4*)(Whh + (size_t)(j0 + Hsz) * Hsz);
    const float4* __restrict__ WN0 = (const float4*)(Whh + (size_t)(j0 + 2*Hsz) * Hsz);
    const float4* __restrict__ WR1 = (const float4*)(Whh + (size_t)j1 * Hsz);
    const float4* __restrict__ WZ1 = (const float4*)(Whh + (size_t)(j1 + Hsz) * Hsz);
    const float4* __restrict__ WN1 = (const float4*)(Whh + (size_t)(j1 + 2*Hsz) * Hsz);

    const float bR0 = bhh[j0], bZ0 = bhh[j0 + Hsz], bN0 = bhh[j0 + 2*Hsz];
    const float bR1 = bhh[j1], bZ1 = bhh[j1 + Hsz], bN1 = bhh[j1 + 2*Hsz];

    float sum0[Rr], sum1[Rr];
    #pragma unroll
    for (int r = 0; r < Rr; r++) { sum0[r] = 0.f; sum1[r] = 0.f; }

    __syncthreads();

    float* hcur = &hsA[0][0];
    float* hnxt = &hsB[0][0];

    for (int t = 0; t < Ssz; t++) {
        float aR0[Rr], aZ0[Rr], aN0[Rr], aR1[Rr], aZ1[Rr], aN1[Rr];
        #pragma unroll
        for (int r = 0; r < Rr; r++) {
            aR0[r] = 0.f; aZ0[r] = 0.f; aN0[r] = 0.f;
            aR1[r] = 0.f; aZ1[r] = 0.f; aN1[r] = 0.f;
        }
        const float4* h4 = (const float4*)hcur;
        #pragma unroll 2
        for (int k4 = 0; k4 < Hsz / 4; k4++) {
            float4 wr0 = WR0[k4], wz0 = WZ0[k4], wn0 = WN0[k4];
            float4 wr1 = WR1[k4], wz1 = WZ1[k4], wn1 = WN1[k4];
            #pragma unroll
            for (int r = 0; r < Rr; r++) {
                float4 hv = h4[r * (Hsz/4) + k4];   // broadcast across warp
                aR0[r] = dot4(wr0, hv, aR0[r]);
                aZ0[r] = dot4(wz0, hv, aZ0[r]);
                aN0[r] = dot4(wn0, hv, aN0[r]);
                aR1[r] = dot4(wr1, hv, aR1[r]);
                aZ1[r] = dot4(wz1, hv, aZ1[r]);
                aN1[r] = dot4(wn1, hv, aN1[r]);
            }
        }
        const int tsrc = dir ? (Ssz - 1 - t) : t;   // backward reads reversed x
        #pragma unroll
        for (int r = 0; r < Rr; r++) {
            const float* __restrict__ gi =
                GIb + ((size_t)(b0 + r) * Ssz + tsrc) * Gsz;
            const float m = (t < slen[r]) ? 1.f : 0.f;   // forward-index mask
            {
                float rg = sigm(gi[j0]         + aR0[r] + bR0);
                float zg = sigm(gi[j0 + Hsz]   + aZ0[r] + bZ0);
                float ng = tanhf(gi[j0 + 2*Hsz] + rg * (aN0[r] + bN0));
                float hv = hcur[r * Hsz + j0];
                float hn = ng + zg * (hv - ng);    // (1-z)*n + z*h
                hnxt[r * Hsz + j0] = hn;
                sum0[r] += hn * m;
            }
            {
                float rg = sigm(gi[j1]         + aR1[r] + bR1);
                float zg = sigm(gi[j1 + Hsz]   + aZ1[r] + bZ1);
                float ng = tanhf(gi[j1 + 2*Hsz] + rg * (aN1[r] + bN1));
                float hv = hcur[r * Hsz + j1];
                float hn = ng + zg * (hv - ng);
                hnxt[r * Hsz + j1] = hn;
                sum1[r] += hn * m;
            }
        }
        __syncthreads();
        float* tp = hcur; hcur = hnxt; hnxt = tp;
    }
    #pragma unroll
    for (int r = 0; r < Rr; r++) {
        g_part[((size_t)dir * Bsz + b0 + r) * Hsz + j0] = sum0[r];
        g_part[((size_t)dir * Bsz + b0 + r) * Hsz + j1] = sum1[r];
    }
}

// ---------------------------------------------------------------------------
// Kernel 3: avg = 0.5*(sum_f + sum_b)/len; mu/sigma heads; reparam sample.
// Output layout: [final (B*Z) | mu (B*Z) | sigma (B*Z)]
// ---------------------------------------------------------------------------
__global__ __launch_bounds__(128) void k_head(
    const float* __restrict__ Wmu, const float* __restrict__ bmu,
    const float* __restrict__ Wsg, const float* __restrict__ bsg,
    const float* __restrict__ eps, const int* __restrict__ lens,
    float* __restrict__ out)
{
    __shared__ float avg[Hsz];
    const int b = blockIdx.x;
    const int tid = threadIdx.x;
    const float inv = 0.5f / (float)lens[b];   // mask.sum(0) == len (len <= S)
    for (int i = tid; i < Hsz; i += 128)
        avg[i] = (g_part[(size_t)b * Hsz + i] +
                  g_part[((size_t)Bsz + b) * Hsz + i]) * inv;
    __syncthreads();

    const float4* a4 = (const float4*)avg;
    const float4* wm = (const float4*)(Wmu + (size_t)tid * Hsz);
    const float4* ws = (const float4*)(Wsg + (size_t)tid * Hsz);
    float sm = 0.f, ss = 0.f;
    #pragma unroll 4
    for (int i = 0; i < Hsz / 4; i++) {
        float4 a = a4[i];
        sm = dot4(wm[i], a, sm);
        ss = dot4(ws[i], a, ss);
    }
    sm += bmu[tid];
    ss += bsg[tid];
    float mu = (sm >= 0.f) ? sm : 0.2f * sm;   // leaky relu 0.2
    float ls = (ss >= 0.f) ? ss : 0.2f * ss;
    float sg = expf(ls);
    float fin = fmaf(eps[(size_t)b * Zsz + tid], sg, mu);
    out[(size_t)b * Zsz + tid]              = fin;
    out[((size_t)Bsz + b) * Zsz + tid]      = mu;
    out[((size_t)2 * Bsz + b) * Zsz + tid]  = sg;
}

extern "C" void kernel_launch(void* const* d_in, const int* in_sizes, int n_in,
                              void* d_out, int out_size)
{
    const float* text  = (const float*)d_in[0];
    const int*   lens  = (const int*)  d_in[1];
    const float* Wih_f = (const float*)d_in[2];
    const float* Whh_f = (const float*)d_in[3];
    const float* bih_f = (const float*)d_in[4];
    const float* bhh_f = (const float*)d_in[5];
    const float* Wih_b = (const float*)d_in[6];
    const float* Whh_b = (const float*)d_in[7];
    const float* bih_b = (const float*)d_in[8];
    const float* bhh_b = (const float*)d_in[9];
    const float* W_mu  = (const float*)d_in[10];
    const float* b_mu  = (const float*)d_in[11];
    const float* W_sig = (const float*)d_in[12];
    const float* b_sig = (const float*)d_in[13];
    const float* eps   = (const float*)d_in[14];
    float* out = (float*)d_out;

    // 1) GI = x @ Wih.T + bih for both directions (one fused GEMM grid)
    k_gi_gemm<<<dim3(MR / 128, (2 * Gsz) / 64), 256>>>(text, Wih_f, bih_f, Wih_b, bih_b);
    // 2) GRU scan, both directions in parallel across CTAs
    k_gru<<<dim3(Bsz / Rr, 2), 256>>>(Whh_f, bhh_f, Whh_b, bhh_b, lens);
    // 3) Average + VAE heads + reparameterized sample
    k_head<<<Bsz, 128>>>(W_mu, b_mu, W_sig, b_sig, eps, lens, out);
}

// round 3
// speedup vs baseline: 1.0020x; 1.0020x over previous
#include <cuda_runtime.h>
#include <math.h>
#include <stddef.h>

namespace {
constexpr int Bsz = 1024;
constexpr int Ssz = 64;
constexpr int Dsz = 300;
constexpr int Hsz = 512;
constexpr int Gsz = 1536;   // 3H
constexpr int Zsz = 128;
constexpr int MR  = Bsz * Ssz;   // 65536
constexpr int Rr  = 8;           // batch rows per GRU CTA
}

// Scratch (allocation-free rule: __device__ globals)
__device__ float g_GI[(size_t)2 * MR * Gsz];      // [dir][b*S + t_src][3H], ~805 MB
__device__ float g_part[(size_t)2 * Bsz * Hsz];   // masked hidden sums per direction

__device__ __forceinline__ float dot4(float4 w, float4 h, float a) {
    a = fmaf(w.x, h.x, a);
    a = fmaf(w.y, h.y, a);
    a = fmaf(w.z, h.z, a);
    a = fmaf(w.w, h.w, a);
    return a;
}

__device__ __forceinline__ float sigm(float x) {
    return 1.f / (1.f + __expf(-x));
}

// ---------------------------------------------------------------------------
// Kernel 1: GI = X @ Wih.T + bih for BOTH directions in one GEMM.
// M = B*S = 65536, N = 2*1536 = 3072 (n<1536 -> fwd weights, else bwd), K = 300.
// Tiles: BM=128, BN=64, BK=8, 256 threads, 8x4 per-thread tile.
// ---------------------------------------------------------------------------
__global__ __launch_bounds__(256) void k_gi_gemm(
    const float* __restrict__ X,
    const float* __restrict__ Wf, const float* __restrict__ bf,
    const float* __restrict__ Wb, const float* __restrict__ bb)
{
    __shared__ float As[8][128];
    __shared__ float Bs[8][64];
    const int tid = threadIdx.x;
    const int m0 = blockIdx.x * 128;
    const int n0 = blockIdx.y * 64;
    const int dir = (n0 >= Gsz) ? 1 : 0;
    const float* __restrict__ W    = dir ? Wb : Wf;
    const float* __restrict__ bias = dir ? bb : bf;
    const int g0 = n0 - dir * Gsz;

    const int tx = tid & 15;   // 16 col-groups of 4
    const int ty = tid >> 4;   // 16 row-groups of 8

    float acc[8][4];
    #pragma unroll
    for (int i = 0; i < 8; i++)
        #pragma unroll
        for (int j = 0; j < 4; j++) acc[i][j] = 0.f;

    const int arow = tid >> 1;
    const int half = tid & 1;
    const int brow = (tid & 127) >> 1;

    const float* aptr = X + (size_t)(m0 + arow) * Dsz + half * 4;
    const float* bptr = W + (size_t)(g0 + brow) * Dsz + half * 4;

    for (int k0 = 0; k0 < Dsz; k0 += 8) {
        float4 av = make_float4(0.f, 0.f, 0.f, 0.f);
        if (k0 + half * 4 < Dsz) av = *(const float4*)(aptr + k0);
        As[half*4+0][arow] = av.x;
        As[half*4+1][arow] = av.y;
        As[half*4+2][arow] = av.z;
        As[half*4+3][arow] = av.w;
        if (tid < 128) {
            float4 bv = make_float4(0.f, 0.f, 0.f, 0.f);
            if (k0 + half * 4 < Dsz) bv = *(const float4*)(bptr + k0);
            Bs[half*4+0][brow] = bv.x;
            Bs[half*4+1][brow] = bv.y;
            Bs[half*4+2][brow] = bv.z;
            Bs[half*4+3][brow] = bv.w;
        }
        __syncthreads();
        #pragma unroll
        for (int kk = 0; kk < 8; kk++) {
            float4 a0 = *(const float4*)&As[kk][ty*8];
            float4 a1 = *(const float4*)&As[kk][ty*8+4];
            float4 b  = *(const float4*)&Bs[kk][tx*4];
            float a[8] = {a0.x, a0.y, a0.z, a0.w, a1.x, a1.y, a1.z, a1.w};
            #pragma unroll
            for (int i = 0; i < 8; i++) {
                acc[i][0] = fmaf(a[i], b.x, acc[i][0]);
                acc[i][1] = fmaf(a[i], b.y, acc[i][1]);
                acc[i][2] = fmaf(a[i], b.z, acc[i][2]);
                acc[i][3] = fmaf(a[i], b.w, acc[i][3]);
            }
        }
        __syncthreads();
    }

    const float4 bv = *(const float4*)(bias + g0 + tx*4);
    #pragma unroll
    for (int i = 0; i < 8; i++) {
        size_t m = (size_t)(m0 + ty*8 + i);
        float4 o;
        o.x = acc[i][0] + bv.x;
        o.y = acc[i][1] + bv.y;
        o.z = acc[i][2] + bv.z;
        o.w = acc[i][3] + bv.w;
        *(float4*)(g_GI + ((size_t)dir * MR + m) * Gsz + g0 + tx*4) = o;
    }
}

// ---------------------------------------------------------------------------
// Kernel 2: GRU recurrence, one CTA per (direction, 8 batch rows).
// Thread tid owns hidden units j0=tid and j1=tid+256; accumulates the three
// gate dot-products (r,z,n) against smem-resident h for all 8 rows.
// Double-buffered h in smem -> one __syncthreads per step.
// Accumulates masked sum of h over steps (roll/reverse is sum-invariant).
// ---------------------------------------------------------------------------
__global__ __launch_bounds__(256) void k_gru(
    const float* __restrict__ Whh_f, const float* __restrict__ bhh_f,
    const float* __restrict__ Whh_b, const float* __restrict__ bhh_b,
    const int* __restrict__ lens)
{
    __shared__ float hsA[Rr][Hsz];
    __shared__ float hsB[Rr][Hsz];
    __shared__ int slen[Rr];

    const int tid = threadIdx.x;
    const int dir = blockIdx.y;
    const int b0 = blockIdx.x * Rr;
    const float* __restrict__ Whh = dir ? Whh_b : Whh_f;
    const float* __restrict__ bhh = dir ? bhh_b : bhh_f;
    const float* __restrict__ GIb = g_GI + (size_t)dir * MR * Gsz;

    if (tid < Rr) slen[tid] = lens[b0 + tid];
    for (int i = tid; i < Rr * Hsz; i += 256) (&hsA[0][0])[i] = 0.f;

    const int j0 = tid;
    const int j1 = tid + 256;

    const float4* __restrict__ WR0 = (const float4*)(Whh + (size_t)j0 * Hsz);
    const float4* __restrict__ WZ0 = (const float4*)(Whh + (size_t)(j0 + Hsz) * Hsz);
    const float4* __restrict__ WN0 = (const float4*)(Whh + (size_t)(j0 + 2*Hsz) * Hsz);
    const float4* __restrict__ WR1 = (const float4*)(Whh + (size_t)j1 * Hsz);
    const float4* __restrict__ WZ1 = (const float4*)(Whh + (size_t)(j1 + Hsz) * Hsz);
    const float4* __restrict__ WN1 = (const float4*)(Whh + (size_t)(j1 + 2*Hsz) * Hsz);

    const float bR0 = bhh[j0], bZ0 = bhh[j0 + Hsz], bN0 = bhh[j0 + 2*Hsz];
    const float bR1 = bhh[j1], bZ1 = bhh[j1 + Hsz], bN1 = bhh[j1 + 2*Hsz];

    float sum0[Rr], sum1[Rr];
    #pragma unroll
    for (int r = 0; r < Rr; r++) { sum0[r] = 0.f; sum1[r] = 0.f; }

    __syncthreads();

    float* hcur = &hsA[0][0];
    float* hnxt = &hsB[0][0];

    for (int t = 0; t < Ssz; t++) {
        float aR0[Rr], aZ0[Rr], aN0[Rr], aR1[Rr], aZ1[Rr], aN1[Rr];
        #pragma unroll
        for (int r = 0; r < Rr; r++) {
            aR0[r] = 0.f; aZ0[r] = 0.f; aN0[r] = 0.f;
            aR1[r] = 0.f; aZ1[r] = 0.f; aN1[r] = 0.f;
        }
        const float4* h4 = (const float4*)hcur;
        #pragma unroll 2
        for (int k4 = 0; k4 < Hsz / 4; k4++) {
            float4 wr0 = WR0[k4], wz0 = WZ0[k4], wn0 = WN0[k4];
            float4 wr1 = WR1[k4], wz1 = WZ1[k4], wn1 = WN1[k4];
            #pragma unroll
            for (int r = 0; r < Rr; r++) {
                float4 hv = h4[r * (Hsz/4) + k4];   // broadcast across warp
                aR0[r] = dot4(wr0, hv, aR0[r]);
                aZ0[r] = dot4(wz0, hv, aZ0[r]);
                aN0[r] = dot4(wn0, hv, aN0[r]);
                aR1[r] = dot4(wr1, hv, aR1[r]);
                aZ1[r] = dot4(wz1, hv, aZ1[r]);
                aN1[r] = dot4(wn1, hv, aN1[r]);
            }
        }
        const int tsrc = dir ? (Ssz - 1 - t) : t;   // backward reads reversed x
        #pragma unroll
        for (int r = 0; r < Rr; r++) {
            const float* __restrict__ gi =
                GIb + ((size_t)(b0 + r) * Ssz + tsrc) * Gsz;
            const float m = (t < slen[r]) ? 1.f : 0.f;   // forward-index mask
            {
                float rg = sigm(gi[j0]         + aR0[r] + bR0);
                float zg = sigm(gi[j0 + Hsz]   + aZ0[r] + bZ0);
                float ng = tanhf(gi[j0 + 2*Hsz] + rg * (aN0[r] + bN0));
                float hv = hcur[r * Hsz + j0];
                float hn = ng + zg * (hv - ng);    // (1-z)*n + z*h
                hnxt[r * Hsz + j0] = hn;
                sum0[r] += hn * m;
            }
            {
                float rg = sigm(gi[j1]         + aR1[r] + bR1);
                float zg = sigm(gi[j1 + Hsz]   + aZ1[r] + bZ1);
                float ng = tanhf(gi[j1 + 2*Hsz] + rg * (aN1[r] + bN1));
                float hv = hcur[r * Hsz + j1];
                float hn = ng + zg * (hv - ng);
                hnxt[r * Hsz + j1] = hn;
                sum1[r] += hn * m;
            }
        }
        __syncthreads();
        float* tp = hcur; hcur = hnxt; hnxt = tp;
    }
    #pragma unroll
    for (int r = 0; r < Rr; r++) {
        g_part[((size_t)dir * Bsz + b0 + r) * Hsz + j0] = sum0[r];
        g_part[((size_t)dir * Bsz + b0 + r) * Hsz + j1] = sum1[r];
    }
}

// ---------------------------------------------------------------------------
// Kernel 3: avg = 0.5*(sum_f + sum_b)/len; mu/sigma heads; reparam sample.
// Output layout: [final (B*Z) | mu (B*Z) | sigma (B*Z)]
// ---------------------------------------------------------------------------
__global__ __launch_bounds__(128) void k_head(
    const float* __restrict__ Wmu, const float* __restrict__ bmu,
    const float* __restrict__ Wsg, const float* __restrict__ bsg,
    const float* __restrict__ eps, const int* __restrict__ lens,
    float* __restrict__ out)
{
    __shared__ float avg[Hsz];
    const int b = blockIdx.x;
    const int tid = threadIdx.x;
    const float inv = 0.5f / (float)lens[b];   // mask.sum(0) == len (len <= S)
    for (int i = tid; i < Hsz; i += 128)
        avg[i] = (g_part[(size_t)b * Hsz + i] +
                  g_part[((size_t)Bsz + b) * Hsz + i]) * inv;
    __syncthreads();

    const float4* a4 = (const float4*)avg;
    const float4* wm = (const float4*)(Wmu + (size_t)tid * Hsz);
    const float4* ws = (const float4*)(Wsg + (size_t)tid * Hsz);
    float sm = 0.f, ss = 0.f;
    #pragma unroll 4
    for (int i = 0; i < Hsz / 4; i++) {
        float4 a = a4[i];
        sm = dot4(wm[i], a, sm);
        ss = dot4(ws[i], a, ss);
    }
    sm += bmu[tid];
    ss += bsg[tid];
    float mu = (sm >= 0.f) ? sm : 0.2f * sm;   // leaky relu 0.2
    float ls = (ss >= 0.f) ? ss : 0.2f * ss;
    float sg = expf(ls);
    float fin = fmaf(eps[(size_t)b * Zsz + tid], sg, mu);
    out[(size_t)b * Zsz + tid]              = fin;
    out[((size_t)Bsz + b) * Zsz + tid]      = mu;
    out[((size_t)2 * Bsz + b) * Zsz + tid]  = sg;
}

extern "C" void kernel_launch(void* const* d_in, const int* in_sizes, int n_in,
                              void* d_out, int out_size)
{
    const float* text  = (const float*)d_in[0];
    const int*   lens  = (const int*)  d_in[1];
    const float* Wih_f = (const float*)d_in[2];
    const float* Whh_f = (const float*)d_in[3];
    const float* bih_f = (const float*)d_in[4];
    const float* bhh_f = (const float*)d_in[5];
    const float* Wih_b = (const float*)d_in[6];
    const float* Whh_b = (const float*)d_in[7];
    const float* bih_b = (const float*)d_in[8];
    const float* bhh_b = (const float*)d_in[9];
    const float* W_mu  = (const float*)d_in[10];
    const float* b_mu  = (const float*)d_in[11];
    const float* W_sig = (const float*)d_in[12];
    const float* b_sig = (const float*)d_in[13];
    const float* eps   = (const float*)d_in[14];
    float* out = (float*)d_out;

    // 1) GI = x @ Wih.T + bih for both directions (one fused GEMM grid)
    k_gi_gemm<<<dim3(MR / 128, (2 * Gsz) / 64), 256>>>(text, Wih_f, bih_f, Wih_b, bih_b);
    // 2) GRU scan, both directions in parallel across CTAs
    k_gru<<<dim3(Bsz / Rr, 2), 256>>>(Whh_f, bhh_f, Whh_b, bhh_b, lens);
    // 3) Average + VAE heads + reparameterized sample
    k_head<<<Bsz, 128>>>(W_mu, b_mu, W_sig, b_sig, eps, lens, out);
}